// round 4
// baseline (speedup 1.0000x reference)
#include <cuda_runtime.h>
#include <cuda_bf16.h>
#include <stdint.h>

// ---------------------------------------------------------------------------
// Phase 1 (sub2): one block per type column c.
//   edges for column c are contiguous: [c*deg2, (c+1)*deg2)   (col2 sorted)
//   out[rc[c]][d] = emb[rc[c]][d] + (n_ent - deg2) + sum_e emb[ls[s2r[e]]][d]
// blockDim.x == D (128). Edge row indices staged in shared memory.
// ---------------------------------------------------------------------------
__global__ void sub2_kernel(const float* __restrict__ emb,
                            const int*   __restrict__ s2r,
                            const int*   __restrict__ ls,
                            const int*   __restrict__ rc,
                            float*       __restrict__ out,
                            int deg2, int n_ent, int D)
{
    extern __shared__ int rows[];
    const int c = blockIdx.x;
    for (int i = threadIdx.x; i < deg2; i += blockDim.x)
        rows[i] = ls[s2r[(size_t)c * deg2 + i]];
    __syncthreads();

    const int d = threadIdx.x;
    float acc = (float)n_ent - (float)deg2;
    #pragma unroll 8
    for (int e = 0; e < deg2; ++e)
        acc += emb[(size_t)rows[e] * D + d];

    const int t = rc[c];
    out[(size_t)t * D + d] = emb[(size_t)t * D + d] + acc;
}

// ---------------------------------------------------------------------------
// Phase 2 (sub3): one (D/4)-lane group per entity, float4 vectorized.
//   edges for entity c are contiguous: [c*deg3, (c+1)*deg3)  (col3 sorted)
//   acc = (n_typ - deg3) + sum_e out[lc[s3r[e]]]   (type rows updated by sub2)
//   out[rs[c]] = emb[rs[c]] * (1 - acc / (1 + deg3))
// Type rows (read) and entity rows (written) are disjoint -> no hazard.
// blockDim.x must be a multiple of D/4.
// ---------------------------------------------------------------------------
__global__ void sub3_kernel(const float* __restrict__ emb,
                            const int*   __restrict__ s3r,
                            const int*   __restrict__ lc,
                            const int*   __restrict__ rs,
                            float*       out,
                            int deg3, int n_typ, int n_ent, int D)
{
    const int tpe  = D >> 2;                       // threads per entity (32 for D=128)
    const int epb  = blockDim.x / tpe;             // entities per block
    const int ent  = blockIdx.x * epb + threadIdx.x / tpe;
    const int lane = threadIdx.x % tpe;
    if (ent >= n_ent) return;

    const float base = (float)n_typ - (float)deg3;
    float4 acc = make_float4(base, base, base, base);

    const int* er = s3r + (size_t)ent * deg3;
    const float4* out4 = (const float4*)out;
    #pragma unroll 4
    for (int e = 0; e < deg3; ++e) {
        const int tr = lc[er[e]];                  // same addr across the group -> L1 broadcast
        float4 v = out4[(size_t)tr * tpe + lane];  // type row: L2-resident (512 KB set)
        acc.x += v.x; acc.y += v.y; acc.z += v.z; acc.w += v.w;
    }

    const float inv = 1.0f / (1.0f + (float)deg3);
    const int t = rs[ent];
    float4 iv = ((const float4*)emb)[(size_t)t * tpe + lane];
    float4 r;
    r.x = iv.x * (1.0f - acc.x * inv);
    r.y = iv.y * (1.0f - acc.y * inv);
    r.z = iv.z * (1.0f - acc.z * inv);
    r.w = iv.w * (1.0f - acc.w * inv);
    ((float4*)out)[(size_t)t * tpe + lane] = r;
}

// ---------------------------------------------------------------------------
// Inputs (metadata order):
//  0 all_node_embedding f32 [(n_ent+n_typ)*D]
//  1 sub2_row i32   2 sub2_col i32   3 sub3_row i32   4 sub3_col i32
//  5 left_specific i32 [n_ent]   6 right_common i32 [n_typ]
//  7 left_common  i32 [n_typ]    8 right_specific i32 [n_ent]
// Output: f32 [(n_ent+n_typ)*D]. Every row is written by exactly one of the
// two kernels (type rows by sub2, entity rows by sub3) -> no copy kernel.
// ---------------------------------------------------------------------------
extern "C" void kernel_launch(void* const* d_in, const int* in_sizes, int n_in,
                              void* d_out, int out_size)
{
    const float* emb = (const float*)d_in[0];
    const int*   s2r = (const int*)d_in[1];
    const int*   s3r = (const int*)d_in[3];
    const int*   ls  = (const int*)d_in[5];
    const int*   rc  = (const int*)d_in[6];
    const int*   lc  = (const int*)d_in[7];
    const int*   rs  = (const int*)d_in[8];
    float* out = (float*)d_out;

    const int n_ent = in_sizes[5];
    const int n_typ = in_sizes[7];
    const int D     = in_sizes[0] / (n_ent + n_typ);   // 128
    const int deg2  = in_sizes[1] / n_typ;             // 64
    const int deg3  = in_sizes[3] / n_ent;             // 4

    // Phase 1: type rows
    sub2_kernel<<<n_typ, D, deg2 * (int)sizeof(int)>>>(
        emb, s2r, ls, rc, out, deg2, n_ent, D);

    // Phase 2: entity rows (reads updated type rows from `out`)
    const int tpe = D >> 2;            // 32
    const int block = 256;             // 8 entities per block
    const int epb = block / tpe;
    const int grid = (n_ent + epb - 1) / epb;
    sub3_kernel<<<grid, block>>>(
        emb, s3r, lc, rs, out, deg3, n_typ, n_ent, D);
}

// round 6
// speedup vs baseline: 1.4568x; 1.4568x over previous
#include <cuda_runtime.h>
#include <cuda_bf16.h>
#include <stdint.h>

// ===========================================================================
// Phase 1 (sub2), fast path: deg2==64, D==128.
// One block (128 thr) per type column. Warp w sums edges {w, w+4, ...} (16
// rows) with float4 loads (32 lanes cover the 512B row), smem reduce across
// the 4 warps, warp 0 writes the type row.
// ===========================================================================
__global__ void sub2_f4_kernel(const float4* __restrict__ emb4,
                               const int*    __restrict__ s2r,
                               const int*    __restrict__ ls,
                               const int*    __restrict__ rc,
                               float4*       __restrict__ out4,
                               int n_ent)
{
    __shared__ int    rows[64];
    __shared__ float4 part[3][32];

    const int c    = blockIdx.x;
    const int t    = threadIdx.x;
    const int lane = t & 31;
    const int w    = t >> 5;

    if (t < 64) rows[t] = ls[__ldg(s2r + c * 64 + t)];
    __syncthreads();

    float4 acc = make_float4(0.f, 0.f, 0.f, 0.f);
    #pragma unroll
    for (int e = 0; e < 16; ++e) {
        const int r = rows[e * 4 + w];
        float4 v = __ldg(emb4 + (size_t)r * 32 + lane);
        acc.x += v.x; acc.y += v.y; acc.z += v.z; acc.w += v.w;
    }

    if (w > 0) part[w - 1][lane] = acc;
    __syncthreads();

    if (w == 0) {
        #pragma unroll
        for (int i = 0; i < 3; ++i) {
            float4 p = part[i][lane];
            acc.x += p.x; acc.y += p.y; acc.z += p.z; acc.w += p.w;
        }
        const float base = (float)n_ent - 64.0f;
        const int   tr   = __ldg(rc + c);
        float4 iv = __ldg(emb4 + (size_t)tr * 32 + lane);
        float4 r;
        r.x = iv.x + acc.x + base;
        r.y = iv.y + acc.y + base;
        r.z = iv.z + acc.z + base;
        r.w = iv.w + acc.w + base;
        out4[(size_t)tr * 32 + lane] = r;
    }
}

// Generic fallback (any deg2 / D): one thread per embedding dim.
__global__ void sub2_gen_kernel(const float* __restrict__ emb,
                                const int*   __restrict__ s2r,
                                const int*   __restrict__ ls,
                                const int*   __restrict__ rc,
                                float*       __restrict__ out,
                                int deg2, int n_ent, int D)
{
    extern __shared__ int rows[];
    const int c = blockIdx.x;
    for (int i = threadIdx.x; i < deg2; i += blockDim.x)
        rows[i] = ls[s2r[(size_t)c * deg2 + i]];
    __syncthreads();

    const int d = threadIdx.x;
    if (d >= D) return;
    float acc = (float)n_ent - (float)deg2;
    #pragma unroll 8
    for (int e = 0; e < deg2; ++e)
        acc += emb[(size_t)rows[e] * D + d];
    const int t = rc[c];
    out[(size_t)t * D + d] = emb[(size_t)t * D + d] + acc;
}

// ===========================================================================
// Phase 2 (sub3), fast path: deg3==4, D==128.
// One warp per entity: int4 edge-index load (1 LDG instead of 4), 4 broadcast
// lc loads, 4 independent float4 type-row loads (L2-resident, keep cached),
// streaming (__ldcs/__stcs) for the touch-once entity rows so the 205 MB
// stream doesn't evict the 512 KB type table from L2.
// ===========================================================================
__global__ void sub3_f4_kernel(const float4* __restrict__ emb4,
                               const int4*   __restrict__ s3r4,
                               const int*    __restrict__ lc,
                               const int*    __restrict__ rs,
                               float4*       out4,
                               int n_typ, int n_ent)
{
    const int ent  = blockIdx.x * 8 + (threadIdx.x >> 5);
    const int lane = threadIdx.x & 31;
    if (ent >= n_ent) return;

    const int4 e4 = __ldg(s3r4 + ent);
    const int t0 = __ldg(lc + e4.x);
    const int t1 = __ldg(lc + e4.y);
    const int t2 = __ldg(lc + e4.z);
    const int t3 = __ldg(lc + e4.w);

    // Type rows: hot 512 KB set, default cached loads (L1+L2).
    float4 v0 = out4[(size_t)t0 * 32 + lane];
    float4 v1 = out4[(size_t)t1 * 32 + lane];
    float4 v2 = out4[(size_t)t2 * 32 + lane];
    float4 v3 = out4[(size_t)t3 * 32 + lane];

    const float base = (float)n_typ - 4.0f;
    float4 acc;
    acc.x = base + v0.x + v1.x + v2.x + v3.x;
    acc.y = base + v0.y + v1.y + v2.y + v3.y;
    acc.z = base + v0.z + v1.z + v2.z + v3.z;
    acc.w = base + v0.w + v1.w + v2.w + v3.w;

    const int tr = __ldg(rs + ent);
    // Streaming entity row: evict-first read + streaming store.
    float4 iv = __ldcs(emb4 + (size_t)tr * 32 + lane);
    const float inv = 0.2f;  // 1/(1+deg3)
    float4 r;
    r.x = iv.x * (1.0f - acc.x * inv);
    r.y = iv.y * (1.0f - acc.y * inv);
    r.z = iv.z * (1.0f - acc.z * inv);
    r.w = iv.w * (1.0f - acc.w * inv);
    __stcs(out4 + (size_t)tr * 32 + lane, r);
}

// Generic fallback.
__global__ void sub3_gen_kernel(const float* __restrict__ emb,
                                const int*   __restrict__ s3r,
                                const int*   __restrict__ lc,
                                const int*   __restrict__ rs,
                                float*       out,
                                int deg3, int n_typ, int n_ent, int D)
{
    const int tpe  = D >> 2;
    const int epb  = blockDim.x / tpe;
    const int ent  = blockIdx.x * epb + threadIdx.x / tpe;
    const int lane = threadIdx.x % tpe;
    if (ent >= n_ent) return;

    const float base = (float)n_typ - (float)deg3;
    float4 acc = make_float4(base, base, base, base);
    const int* er = s3r + (size_t)ent * deg3;
    const float4* out4 = (const float4*)out;
    for (int e = 0; e < deg3; ++e) {
        const int t = lc[er[e]];
        float4 v = out4[(size_t)t * tpe + lane];
        acc.x += v.x; acc.y += v.y; acc.z += v.z; acc.w += v.w;
    }
    const float inv = 1.0f / (1.0f + (float)deg3);
    const int t = rs[ent];
    float4 iv = ((const float4*)emb)[(size_t)t * tpe + lane];
    float4 r;
    r.x = iv.x * (1.0f - acc.x * inv);
    r.y = iv.y * (1.0f - acc.y * inv);
    r.z = iv.z * (1.0f - acc.z * inv);
    r.w = iv.w * (1.0f - acc.w * inv);
    ((float4*)out)[(size_t)t * tpe + lane] = r;
}

// ===========================================================================
// Inputs (metadata order):
//  0 all_node_embedding f32 [(n_ent+n_typ)*D]
//  1 sub2_row i32   2 sub2_col i32   3 sub3_row i32   4 sub3_col i32
//  5 left_specific i32 [n_ent]   6 right_common i32 [n_typ]
//  7 left_common  i32 [n_typ]    8 right_specific i32 [n_ent]
// Type rows ∪ entity rows cover the whole output -> no copy kernel.
// ===========================================================================
extern "C" void kernel_launch(void* const* d_in, const int* in_sizes, int n_in,
                              void* d_out, int out_size)
{
    const float* emb = (const float*)d_in[0];
    const int*   s2r = (const int*)d_in[1];
    const int*   s3r = (const int*)d_in[3];
    const int*   ls  = (const int*)d_in[5];
    const int*   rc  = (const int*)d_in[6];
    const int*   lc  = (const int*)d_in[7];
    const int*   rs  = (const int*)d_in[8];
    float* out = (float*)d_out;

    const int n_ent = in_sizes[5];
    const int n_typ = in_sizes[7];
    const int D     = in_sizes[0] / (n_ent + n_typ);   // 128
    const int deg2  = in_sizes[1] / n_typ;             // 64
    const int deg3  = in_sizes[3] / n_ent;             // 4

    // ---- Phase 1: type rows ----
    if (deg2 == 64 && D == 128) {
        sub2_f4_kernel<<<n_typ, 128>>>(
            (const float4*)emb, s2r, ls, rc, (float4*)out, n_ent);
    } else {
        sub2_gen_kernel<<<n_typ, (D + 31) & ~31, deg2 * (int)sizeof(int)>>>(
            emb, s2r, ls, rc, out, deg2, n_ent, D);
    }

    // ---- Phase 2: entity rows (reads updated type rows from `out`) ----
    if (deg3 == 4 && D == 128) {
        const int grid = (n_ent + 7) / 8;
        sub3_f4_kernel<<<grid, 256>>>(
            (const float4*)emb, (const int4*)s3r, lc, rs, (float4*)out,
            n_typ, n_ent);
    } else {
        const int tpe = D >> 2;
        const int block = 256;
        const int epb = block / tpe;
        const int grid = (n_ent + epb - 1) / epb;
        sub3_gen_kernel<<<grid, block>>>(
            emb, s3r, lc, rs, out, deg3, n_typ, n_ent, D);
    }
}